// round 8
// baseline (speedup 1.0000x reference)
#include <cuda_runtime.h>

#define MARGIN 1.0f
#define TPB 256
#define TILE 1024
#define PER (TILE / TPB)   // 4 elements per thread per tile
#define NWARPS (TPB / 32)

// Zero-initialized at module load; last-done block resets them after use so
// every graph replay starts from clean state with no extra reset launch.
__device__ double g_acc;
__device__ int g_pc;
__device__ int g_done;

__global__ void __launch_bounds__(TPB)
aucm_fused_kernel(const float* __restrict__ preds,
                  const int* __restrict__ targets,
                  int n, float* __restrict__ out, int nblocks) {
    __shared__ float sa[TILE];       // compacted (1 - p_j) for positives in tile
    __shared__ int ws[NWARPS];       // warp scan sums
    __shared__ float wp[NWARPS];     // reduction partials

    const int tid = threadIdx.x;
    const int lane = tid & 31;
    const int wid = tid >> 5;

    // This thread owns element t as a candidate NEGATIVE.
    const int t = blockIdx.x * TPB + tid;
    bool is_neg = false;
    float nv = 0.0f;
    if (t < n) {
        is_neg = (targets[t] == 0);
        nv = preds[t];
    }

    // This block handles the POSITIVE tile [j0, j1) — exactly one tile.
    const int j0 = blockIdx.y * TILE;
    const int j1 = min(j0 + TILE, n);

    // Load this tile; flag positives. Fast path: full tile + 16B alignment
    // -> one LDG.128 for preds and one for targets per thread.
    float pv[PER];
    int fl[PER];
    int c = 0;
    const bool full_tile = (j1 - j0 == TILE) &&
                           ((((size_t)preds | (size_t)targets) & 15u) == 0);
    if (full_tile) {
        const float4 p4 = ((const float4*)(preds + j0))[tid];
        const int4 t4 = ((const int4*)(targets + j0))[tid];
        pv[0] = p4.x; pv[1] = p4.y; pv[2] = p4.z; pv[3] = p4.w;
        fl[0] = (t4.x == 1); fl[1] = (t4.y == 1);
        fl[2] = (t4.z == 1); fl[3] = (t4.w == 1);
        c = fl[0] + fl[1] + fl[2] + fl[3];
    } else {
        // Same contiguous-per-thread ordering as the fast path.
        #pragma unroll
        for (int k = 0; k < PER; k++) {
            int j = j0 + tid * PER + k;
            float p = 0.0f;
            int f = 0;
            if (j < j1) {
                p = preds[j];
                f = (targets[j] == 1);
            }
            pv[k] = p;
            fl[k] = f;
            c += f;
        }
    }

    // Block-wide exclusive scan of per-thread positive counts.
    int inc = c;
    #pragma unroll
    for (int off = 1; off < 32; off <<= 1) {
        int u = __shfl_up_sync(0xFFFFFFFFu, inc, off);
        if (lane >= off) inc += u;
    }
    if (lane == 31) ws[wid] = inc;
    __syncthreads();
    if (wid == 0) {
        int v = (lane < NWARPS) ? ws[lane] : 0;
        #pragma unroll
        for (int off = 1; off < NWARPS; off <<= 1) {
            int u = __shfl_up_sync(0xFFFFFFFFu, v, off);
            if (lane >= off) v += u;
        }
        if (lane < NWARPS) ws[lane] = v;   // inclusive over warps
    }
    __syncthreads();
    const int warp_excl = (wid == 0) ? 0 : ws[wid - 1];
    const int tpos = ws[NWARPS - 1];       // positives in this tile
    int wr = warp_excl + inc - c;          // this thread's exclusive prefix

    // Compact (1 - p) of positives into smem.
    #pragma unroll
    for (int k = 0; k < PER; k++) {
        if (fl[k]) sa[wr++] = 1.0f - pv[k];
    }
    __syncthreads();

    // Pair loop: my negative vs all positives of this tile.
    // Two independent accumulator chains for ILP.
    float acc_q = 0.0f;   // sum of d^2
    float acc_r = 0.0f;   // sum of relu(d)
    if (is_neg) {
        #pragma unroll 4
        for (int j = 0; j < tpos; j++) {
            float d = sa[j] + nv;            // 1 - (p - n)
            acc_q = fmaf(d, d, acc_q);       // (1-(p-n))^2
            acc_r += fmaxf(d, 0.0f);         // relu(1-(p-n))
        }
    }
    float acc = fmaf(MARGIN, acc_r, acc_q);

    // Block reduction: warp shuffle, then per-warp partials.
    #pragma unroll
    for (int off = 16; off > 0; off >>= 1)
        acc += __shfl_xor_sync(0xFFFFFFFFu, acc, off);
    if (lane == 0) wp[wid] = acc;
    __syncthreads();

    if (tid == 0) {
        float v = 0.0f;
        #pragma unroll
        for (int w = 0; w < NWARPS; w++) v += wp[w];
        atomicAdd(&g_acc, (double)v);
        if (blockIdx.x == 0) atomicAdd(&g_pc, tpos);  // count each tile once
        __threadfence();                               // release
        int prev = atomicAdd(&g_done, 1);
        if (prev == nblocks - 1) {
            __threadfence();                           // acquire
            int pc = g_pc;
            double denom = (double)pc * (double)(n - pc);
            out[0] = (float)(g_acc / denom);
            // Reset globals for the next graph replay.
            g_acc = 0.0;
            g_pc = 0;
            g_done = 0;
        }
    }
}

extern "C" void kernel_launch(void* const* d_in, const int* in_sizes, int n_in,
                              void* d_out, int out_size) {
    const float* preds = (const float*)d_in[0];
    const int* targets = (const int*)d_in[1];
    float* out = (float*)d_out;
    int n = in_sizes[0];

    dim3 grid((n + TPB - 1) / TPB, (n + TILE - 1) / TILE);
    aucm_fused_kernel<<<grid, TPB>>>(preds, targets, n, out,
                                     (int)(grid.x * grid.y));
}

// round 10
// speedup vs baseline: 1.1866x; 1.1866x over previous
#include <cuda_runtime.h>

#define MARGIN 1.0f
#define TPB 256
#define TILE 1024
#define PER 4              // tile elements per thread (TILE/TPB)
#define NEG_PER 2          // negatives handled per thread
#define NWARPS (TPB / 32)

// Zero-initialized at module load; last-done block resets after use so every
// graph replay starts from clean state with no extra reset launch.
__device__ double g_sabs;                      // sum |a_i + n_j| over pairs
__device__ double g_sa, g_sa2, g_sn, g_sn2;    // class sums
__device__ int g_pc;
__device__ int g_done;

__device__ __forceinline__ float warp_sum(float v) {
    #pragma unroll
    for (int off = 16; off > 0; off >>= 1)
        v += __shfl_xor_sync(0xFFFFFFFFu, v, off);
    return v;
}

__global__ void __launch_bounds__(TPB)
aucm_fused_kernel(const float* __restrict__ preds,
                  const int* __restrict__ targets,
                  int n, float* __restrict__ out, int nblocks) {
    __shared__ float sa[TILE];       // compacted (1 - p) of tile positives
    __shared__ int ws[NWARPS];
    __shared__ float wp[NWARPS];

    const int tid = threadIdx.x;
    const int lane = tid & 31;
    const int wid = tid >> 5;

    // ---- This thread's NEG_PER candidate negatives (contiguous) ----
    const int tbase = (blockIdx.x * TPB + tid) * NEG_PER;
    float nv[NEG_PER];
    int isneg[NEG_PER];
    if (tbase + NEG_PER <= n) {
        const float2 p2 = *(const float2*)(preds + tbase);
        const int2 t2 = *(const int2*)(targets + tbase);
        nv[0] = p2.x; nv[1] = p2.y;
        isneg[0] = (t2.x == 0); isneg[1] = (t2.y == 0);
    } else {
        #pragma unroll
        for (int k = 0; k < NEG_PER; k++) {
            int i = tbase + k;
            nv[k] = (i < n) ? preds[i] : 0.0f;
            isneg[k] = (i < n) ? (targets[i] == 0) : 0;
        }
    }

    // ---- Positive tile [j0, j1) for this block ----
    const int j0 = blockIdx.y * TILE;
    const int j1 = min(j0 + TILE, n);
    float pv[PER];
    int fl[PER];
    int c = 0;
    if (j1 - j0 == TILE) {
        const float4 p4 = ((const float4*)(preds + j0))[tid];
        const int4 t4 = ((const int4*)(targets + j0))[tid];
        pv[0] = p4.x; pv[1] = p4.y; pv[2] = p4.z; pv[3] = p4.w;
        fl[0] = (t4.x == 1); fl[1] = (t4.y == 1);
        fl[2] = (t4.z == 1); fl[3] = (t4.w == 1);
        c = fl[0] + fl[1] + fl[2] + fl[3];
    } else {
        #pragma unroll
        for (int k = 0; k < PER; k++) {
            int j = j0 + tid * PER + k;
            float p = 0.0f; int f = 0;
            if (j < j1) { p = preds[j]; f = (targets[j] == 1); }
            pv[k] = p; fl[k] = f; c += f;
        }
    }

    // ---- Block-wide scan of positive counts -> compaction offsets ----
    int inc = c;
    #pragma unroll
    for (int off = 1; off < 32; off <<= 1) {
        int u = __shfl_up_sync(0xFFFFFFFFu, inc, off);
        if (lane >= off) inc += u;
    }
    if (lane == 31) ws[wid] = inc;
    __syncthreads();
    if (wid == 0) {
        int v = (lane < NWARPS) ? ws[lane] : 0;
        #pragma unroll
        for (int off = 1; off < NWARPS; off <<= 1) {
            int u = __shfl_up_sync(0xFFFFFFFFu, v, off);
            if (lane >= off) v += u;
        }
        if (lane < NWARPS) ws[lane] = v;
    }
    __syncthreads();
    const int warp_excl = (wid == 0) ? 0 : ws[wid - 1];
    const int tpos = ws[NWARPS - 1];
    int wr = warp_excl + inc - c;
    #pragma unroll
    for (int k = 0; k < PER; k++)
        if (fl[k]) sa[wr++] = 1.0f - pv[k];
    __syncthreads();

    // ---- Pairwise part: only sum of |a_i + n_j| is needed ----
    float acc[NEG_PER];
    #pragma unroll
    for (int k = 0; k < NEG_PER; k++) acc[k] = 0.0f;

    const int t4 = tpos >> 2;
    const float4* sa4 = (const float4*)sa;
    for (int jj = 0; jj < t4; jj++) {
        const float4 s = sa4[jj];
        #pragma unroll
        for (int k = 0; k < NEG_PER; k++) {
            acc[k] += fabsf(s.x + nv[k]);
            acc[k] += fabsf(s.y + nv[k]);
            acc[k] += fabsf(s.z + nv[k]);
            acc[k] += fabsf(s.w + nv[k]);
        }
    }
    for (int j = t4 << 2; j < tpos; j++) {
        const float sv = sa[j];
        #pragma unroll
        for (int k = 0; k < NEG_PER; k++)
            acc[k] += fabsf(sv + nv[k]);
    }
    float accsum = 0.0f;
    #pragma unroll
    for (int k = 0; k < NEG_PER; k++)
        accsum += isneg[k] ? acc[k] : 0.0f;

    // ---- Main reduction: block-level (keeps g_sabs atomics at 1/block) ----
    float r = warp_sum(accsum);
    if (lane == 0) wp[wid] = r;
    __syncthreads();
    if (wid == 0) {
        float v = (lane < NWARPS) ? wp[lane] : 0.0f;
        #pragma unroll
        for (int off = NWARPS / 2; off > 0; off >>= 1)
            v += __shfl_xor_sync(0xFFFFFFFFu, v, off);
        if (lane == 0) atomicAdd(&g_sabs, (double)v);
    }

    // ---- Class statistics (counted once: y==0 blocks only) ----
    // Warp-level reduce + direct atomics: no extra barriers on the tail.
    if (blockIdx.y == 0) {
        float s_a = 0.0f, s_a2 = 0.0f, s_n = 0.0f, s_n2 = 0.0f;
        int cp = 0;
        #pragma unroll
        for (int k = 0; k < NEG_PER; k++) {
            int i = tbase + k;
            if (i < n) {
                if (isneg[k]) {
                    s_n += nv[k];
                    s_n2 = fmaf(nv[k], nv[k], s_n2);
                } else {
                    float a = 1.0f - nv[k];
                    s_a += a;
                    s_a2 = fmaf(a, a, s_a2);
                    cp++;
                }
            }
        }
        s_a = warp_sum(s_a);
        s_a2 = warp_sum(s_a2);
        s_n = warp_sum(s_n);
        s_n2 = warp_sum(s_n2);
        #pragma unroll
        for (int off = 16; off > 0; off >>= 1)
            cp += __shfl_xor_sync(0xFFFFFFFFu, cp, off);
        if (lane == 0) {
            atomicAdd(&g_sa, (double)s_a);
            atomicAdd(&g_sa2, (double)s_a2);
            atomicAdd(&g_sn, (double)s_n);
            atomicAdd(&g_sn2, (double)s_n2);
            atomicAdd(&g_pc, cp);
        }
    }
    __syncthreads();   // all contributions of this block are issued

    if (tid == 0) {
        __threadfence();                     // release my contributions
        int prev = atomicAdd(&g_done, 1);
        if (prev == nblocks - 1) {
            __threadfence();                 // acquire all contributions
            double Pp = (double)g_pc;
            double Nn = (double)n - Pp;
            double Sa = g_sa, Sa2 = g_sa2, Sn = g_sn, Sn2 = g_sn2;
            // sum over pairs of d = a_i + n_j  (closed form)
            double Sd = Nn * Sa + Pp * Sn;
            // sum over pairs of d^2            (closed form)
            double Squad = Nn * Sa2 + 2.0 * Sa * Sn + Pp * Sn2;
            // sum over pairs of relu(d) = (Sd + sum|d|) / 2
            double Srelu = 0.5 * (Sd + g_sabs);
            double total = Squad + (double)MARGIN * Srelu;
            out[0] = (float)(total / (Pp * Nn));
            // Reset globals for next graph replay.
            g_sabs = 0.0;
            g_sa = 0.0; g_sa2 = 0.0; g_sn = 0.0; g_sn2 = 0.0;
            g_pc = 0;
            g_done = 0;
        }
    }
}

extern "C" void kernel_launch(void* const* d_in, const int* in_sizes, int n_in,
                              void* d_out, int out_size) {
    const float* preds = (const float*)d_in[0];
    const int* targets = (const int*)d_in[1];
    float* out = (float*)d_out;
    int n = in_sizes[0];

    dim3 grid((n + TPB * NEG_PER - 1) / (TPB * NEG_PER),
              (n + TILE - 1) / TILE);
    aucm_fused_kernel<<<grid, TPB>>>(preds, targets, n, out,
                                     (int)(grid.x * grid.y));
}